// round 5
// baseline (speedup 1.0000x reference)
#include <cuda_runtime.h>
#include <cstdint>
#include <cstddef>

// CTC batch cost (keras ctc_batch_cost), prob-domain forward, exact biased
// power-of-2 rescaling. Warp-specialized: producer warp gathers emission
// factors from a TMA-streamed smem ring into a compact conflict-free staging
// ring; consumer warp runs the serial trellis at 2 LDS/step.
// B=256, T=512, C=256 (blank=255), U=64, S=129.
static constexpr int Bn = 256, Tn = 512, Cn = 256, Un = 64;
static constexpr int BLANK = Cn - 1;
static constexpr float EPSF = 1e-7f;
static constexpr float Kc = 256.f;     // exact power of 2
static constexpr int   BIAS = 48;      // pins working level ~2^48: no FTZ ever

static constexpr int DATA_BYTES = 65536;        // 64 rows x 1KB, 4 x 16KB quarters
static constexpr int VROW  = 272;               // staging row: 64 f32 pairs + vB + pad
static constexpr int VSLOT = 16 * VROW;         // 4352 B per 16-row slot
static constexpr int SMEM_TOTAL = DATA_BYTES + 4 * VSLOT;   // 82944 B

__device__ __forceinline__ void mwait(uint32_t mbar, uint32_t parity) {
    asm volatile(
        "{\n\t.reg .pred P;\n"
        "WL_%=:\n\t"
        "mbarrier.try_wait.parity.acquire.cta.shared::cta.b64 P, [%0], %1, 0x989680;\n\t"
        "@P bra WD_%=;\n\t"
        "bra WL_%=;\n"
        "WD_%=:\n\t}"
        :: "r"(mbar), "r"(parity) : "memory");
}

__device__ __forceinline__ void bulk_fill(uint32_t mbar, uint32_t sdst,
                                          const float* gsrc, int lane) {
    asm volatile(
        "{\n\t.reg .pred P;\n\t"
        "setp.eq.s32 P, %3, 0;\n\t"
        "@P mbarrier.arrive.expect_tx.shared.b64 _, [%0], 16384;\n\t"
        "@P cp.async.bulk.shared::cta.global.mbarrier::complete_tx::bytes [%1], [%2], 16384, [%0];\n\t"
        "}"
        :: "r"(mbar), "r"(sdst), "l"(gsrc), "r"(lane) : "memory");
}

// Lane L owns states 4L..4L+3; a4 = state 128 on lane 31 only (0 elsewhere).
__device__ __forceinline__ void dp_step(float& a0, float& a1, float& a2,
                                        float& a3, float& a4,
                                        float vB, float v0, float v1,
                                        float sk1, float sk3, int lane) {
    float pa3 = __shfl_up_sync(0xffffffffu, a3, 1);
    if (lane == 0) pa3 = 0.f;
    float na0 = (a0 + pa3) * vB;
    float na1 = fmaf(sk1, pa3, a0 + a1) * v0;
    float na2 = (a1 + a2) * vB;
    float na3 = fmaf(sk3, a1, a2 + a3) * v1;
    float na4 = (lane == 31) ? (a3 + a4) * vB : 0.f;
    a0 = na0; a1 = na1; a2 = na2; a3 = na3; a4 = na4;
}

// consumer: load 4 rows of staged factors (conflict-free: LDS.64 + broadcast)
#define LOADVS(R)                                                            \
    { _Pragma("unroll") for (int i_ = 0; i_ < 4; i_++) {                     \
        float2 t_ = *(const float2*)(vsp + ((R) + i_) * VROW + lane * 8);    \
        v0[i_] = t_.x; v1[i_] = t_.y;                                        \
        vB[i_] = *(const float*)(vsp + ((R) + i_) * VROW + 256); } }

#define APPLY()                                                              \
    { uint32_t bb_ = __float_as_uint(bf);                                    \
      int sh_ = (int)(bb_ >> 23) - 127 - BIAS;                               \
      if (sh_ < -120) sh_ = -120;                                            \
      E += sh_;                                                              \
      float r_ = __uint_as_float((uint32_t)(127 - sh_) << 23);               \
      a0 *= r_; a1 *= r_; a2 *= r_; a3 *= r_; a4 *= r_; }

#define DPS(i_) dp_step(a0,a1,a2,a3,a4, vB[i_],v0[i_],v1[i_], sk1,sk3, lane)

#define GRPA(R)                                                              \
    { float vB[4], v0[4], v1[4]; LOADVS(R); APPLY();                         \
      DPS(0); DPS(1); DPS(2); DPS(3);                                        \
      ls = ((a0 + a1) + (a2 + a3)) + a4;                                     \
      ls += __shfl_xor_sync(0xffffffffu, ls, 16); }

#define GRPB(R)                                                              \
    { float vB[4], v0[4], v1[4]; LOADVS(R);                                  \
      DPS(0); ls += __shfl_xor_sync(0xffffffffu, ls, 8);                     \
      DPS(1); ls += __shfl_xor_sync(0xffffffffu, ls, 4);                     \
      DPS(2); ls += __shfl_xor_sync(0xffffffffu, ls, 2);                     \
      DPS(3); ls += __shfl_xor_sync(0xffffffffu, ls, 1);                     \
      bf = ls; }

__global__ void ctc_fwd_kernel(const int* __restrict__ y_true,
                               const float* __restrict__ y_pred,
                               float* __restrict__ out) {
    extern __shared__ char smem_raw[];
    float* stg   = (float*)smem_raw;               // data ring, 64KB
    char*  vbase = smem_raw + DATA_BYTES;          // staging ring, 4 x 4352B
    __shared__ __align__(8) unsigned long long mb[4];

    const int tid = threadIdx.x, wid = tid >> 5, lane = tid & 31;
    const int b = blockIdx.x;
    const float* g = y_pred + (size_t)b * Tn * Cn;
    const uint32_t sbase = (uint32_t)__cvta_generic_to_shared(stg);
    const uint32_t mbase = (uint32_t)__cvta_generic_to_shared(mb);

    if (tid == 0) {
#pragma unroll
        for (int q = 0; q < 4; q++)
            asm volatile("mbarrier.init.shared.b64 [%0], 1;" :: "r"(mbase + 8u * q) : "memory");
        asm volatile("fence.proxy.async.shared::cta;" ::: "memory");
    }
    __syncthreads();

    const int l0 = y_true[b * Un + 2 * lane];
    const int l1 = y_true[b * Un + 2 * lane + 1];
    const int lp = __shfl_up_sync(0xffffffffu, l1, 1);
    const float sk1 = (lane == 0) ? 0.f : ((l0 != lp) ? 1.f : 0.f);
    const float sk3 = (l1 != l0) ? 1.f : 0.f;

    // producer: gather quarter p (rows 16p..16p+15) -> staging slot p%4,
    // then refill its data slot with quarter p+4 (if any).
    auto produce = [&](int p) {
        const int s = p & 3;
        mwait(mbase + 8u * s, (uint32_t)((p >> 2) & 1));
        const float* dq = stg + s * 4096;
        char* vd = vbase + s * VSLOT;
#pragma unroll
        for (int r = 0; r < 16; r++) {
            float pb = dq[r * Cn + BLANK];
            float q0 = dq[r * Cn + l0];
            float q1 = dq[r * Cn + l1];
            float wB = (pb + EPSF) * Kc;
            float w0 = (q0 + EPSF) * Kc;
            float w1 = (q1 + EPSF) * Kc;
            *(float2*)(vd + r * VROW + lane * 8) = make_float2(w0, w1);
            if (lane == 0) *(float*)(vd + r * VROW + 256) = wB;
        }
        if (p < 28) {
            asm volatile("fence.proxy.async.shared::cta;" ::: "memory");
            bulk_fill(mbase + 8u * s, sbase + s * 16384u, g + (p + 4) * 4096, lane);
        }
    };

    float a0 = 0.f, a1 = 0.f, a2 = 0.f, a3 = 0.f, a4 = 0.f;
    float ls = 0.f, bf = 1.f;
    int   E  = 0;

    if (wid == 1) {
#pragma unroll
        for (int q = 0; q < 4; q++)                 // prologue fills: rows 0..63
            bulk_fill(mbase + 8u * q, sbase + q * 16384u, g + q * 4096, lane);
        produce(0);
        produce(1);
    }
    __syncthreads();

    // ---- iteration 0: consumer handles quarter 0 (init + peel + A B A)
    if (wid == 0) {
        const char* vsp = vbase;                    // slot 0
        {   // t = 0 init: alpha0 = p(blank)+eps, alpha1 = p(l0)+eps  (= v/256)
            float2 t0 = *(const float2*)(vsp + lane * 8);
            float  vB0 = *(const float*)(vsp + 256);
            if (lane == 0) { a0 = vB0 * (1.f / 256.f); a1 = t0.x * (1.f / 256.f); }
        }
#pragma unroll
        for (int t = 1; t < 4; t++) {               // rows 1..3 plain
            float2 tv = *(const float2*)(vsp + t * VROW + lane * 8);
            float  vb = *(const float*)(vsp + t * VROW + 256);
            dp_step(a0, a1, a2, a3, a4, vb, tv.x, tv.y, sk1, sk3, lane);
        }
        GRPA(4); GRPB(8); GRPA(12);
    } else {
        produce(2);
    }
    __syncthreads();

    // ---- main: quarters 1..31 (consumer), producer stays 2 ahead
#pragma unroll 1
    for (int q = 1; q < 32; q++) {
        if (wid == 0) {
            const char* vsp = vbase + (q & 3) * VSLOT;
            GRPB(0); GRPA(4); GRPB(8); GRPA(12);
        } else if (q + 2 < 32) {
            produce(q + 2);
        }
        __syncthreads();
    }

    // stored tail = true_tail * 256^511 * 2^-E  (E exactly bookkept)
    if (wid == 0 && lane == 31) {
        const float LN2 = 0.69314718055994530942f;
        out[b] = -(logf(a3 + a4) + (float)(E - 4088) * LN2);
    }
}

extern "C" void kernel_launch(void* const* d_in, const int* in_sizes, int n_in,
                              void* d_out, int out_size) {
    const int* y_true;
    const float* y_pred;
    if (in_sizes[0] == Bn * Un) {
        y_true = (const int*)d_in[0];
        y_pred = (const float*)d_in[1];
    } else {
        y_true = (const int*)d_in[1];
        y_pred = (const float*)d_in[0];
    }
    cudaFuncSetAttribute(ctc_fwd_kernel,
                         cudaFuncAttributeMaxDynamicSharedMemorySize, SMEM_TOTAL);
    ctc_fwd_kernel<<<Bn, 64, SMEM_TOTAL>>>(y_true, y_pred, (float*)d_out);
}

// round 6
// speedup vs baseline: 1.3762x; 1.3762x over previous
#include <cuda_runtime.h>
#include <cstdint>
#include <cstddef>

// CTC batch cost (keras ctc_batch_cost), prob-domain forward, exact biased
// power-of-2 rescaling, cp.async.bulk streaming. 96KB ring = 6 x 16KB quarters
// (16 rows x 1KB each). One warp per batch element; B=256,T=512,C=256,U=64.
static constexpr int Bn = 256, Tn = 512, Cn = 256, Un = 64;
static constexpr int BLANK = Cn - 1;
static constexpr float EPSF = 1e-7f;
static constexpr float Kc = 256.f;      // exact power of 2
static constexpr float EK = 256.f * EPSF;
static constexpr int   BIAS = 48;       // pins working level ~2^48: no FTZ
static constexpr int   NSLOT = 6;
static constexpr int   SMEM_TOTAL = NSLOT * 16384;   // 96KB

__device__ __forceinline__ void mwait(uint32_t mbar, uint32_t parity) {
    asm volatile(
        "{\n\t.reg .pred P;\n"
        "WL_%=:\n\t"
        "mbarrier.try_wait.parity.acquire.cta.shared::cta.b64 P, [%0], %1, 0x989680;\n\t"
        "@P bra WD_%=;\n\t"
        "bra WL_%=;\n"
        "WD_%=:\n\t}"
        :: "r"(mbar), "r"(parity) : "memory");
}

// lane 0 (predicated): expect_tx + 16KB bulk copy gmem->smem
__device__ __forceinline__ void bulk_fill(uint32_t mbar, uint32_t sdst,
                                          const float* gsrc, int lane) {
    asm volatile(
        "{\n\t.reg .pred P;\n\t"
        "setp.eq.s32 P, %3, 0;\n\t"
        "@P mbarrier.arrive.expect_tx.shared.b64 _, [%0], 16384;\n\t"
        "@P cp.async.bulk.shared::cta.global.mbarrier::complete_tx::bytes [%1], [%2], 16384, [%0];\n\t"
        "}"
        :: "r"(mbar), "r"(sdst), "l"(gsrc), "r"(lane) : "memory");
}

// Lane L owns states 4L..4L+3; a4 = state 128 on lane 31 only (0 elsewhere).
__device__ __forceinline__ void dp_step(float& a0, float& a1, float& a2,
                                        float& a3, float& a4,
                                        float vB, float v0, float v1,
                                        float sk1, float sk3, int lane) {
    float pa3 = __shfl_up_sync(0xffffffffu, a3, 1);
    if (lane == 0) pa3 = 0.f;
    float na0 = (a0 + pa3) * vB;
    float na1 = fmaf(sk1, pa3, a0 + a1) * v0;
    float na2 = (a1 + a2) * vB;
    float na3 = fmaf(sk3, a1, a2 + a3) * v1;
    float na4 = (lane == 31) ? (a3 + a4) * vB : 0.f;
    a0 = na0; a1 = na1; a2 = na2; a3 = na3; a4 = na4;
}

// v = fma(p*256 + 256eps): 1 instr per factor; <=1ulp from reference factor.
#define LOADV(SLOT)                                                          \
    { _Pragma("unroll") for (int i_ = 0; i_ < 4; i_++) {                     \
        vB[i_] = fmaf(pB[((SLOT) + i_) * Cn], Kc, EK);                       \
        v0[i_] = fmaf(p0[((SLOT) + i_) * Cn], Kc, EK);                       \
        v1[i_] = fmaf(p1[((SLOT) + i_) * Cn], Kc, EK); } }

#define APPLY()                                                              \
    { uint32_t bb_ = __float_as_uint(bf);                                    \
      int sh_ = (int)(bb_ >> 23) - 127 - BIAS;                               \
      if (sh_ < -120) sh_ = -120;                                            \
      E += sh_;                                                              \
      float r_ = __uint_as_float((uint32_t)(127 - sh_) << 23);               \
      a0 *= r_; a1 *= r_; a2 *= r_; a3 *= r_; a4 *= r_; }

#define DPS(i_) dp_step(a0,a1,a2,a3,a4, vB[i_],v0[i_],v1[i_], sk1,sk3, lane)

#define GRPA(SLOT)                                                           \
    { float vB[4], v0[4], v1[4]; LOADV(SLOT); APPLY();                       \
      DPS(0); DPS(1); DPS(2); DPS(3);                                        \
      ls = ((a0 + a1) + (a2 + a3)) + a4;                                     \
      ls += __shfl_xor_sync(0xffffffffu, ls, 16); }

#define GRPB(SLOT)                                                           \
    { float vB[4], v0[4], v1[4]; LOADV(SLOT);                                \
      DPS(0); ls += __shfl_xor_sync(0xffffffffu, ls, 8);                     \
      DPS(1); ls += __shfl_xor_sync(0xffffffffu, ls, 4);                     \
      DPS(2); ls += __shfl_xor_sync(0xffffffffu, ls, 2);                     \
      DPS(3); ls += __shfl_xor_sync(0xffffffffu, ls, 1);                     \
      bf = ls; }

// quarter q at ring slot SL (rows 16*SL..16*SL+15): wait, maybe refill
// slot (q-1)%6 with quarter q+5, then 16 dp steps (B A B A).
#define QBLK(SL, PAR, RSL, OK)                                               \
    { mwait(mbase + 8u * (SL), (PAR)); __syncwarp();                         \
      if (OK) { bulk_fill(mbase + 8u * (RSL), sbase + (RSL) * 16384u, gR, lane); \
                gR += 4096; }                                                \
      GRPB(16 * (SL)); GRPA(16 * (SL) + 4);                                  \
      GRPB(16 * (SL) + 8); GRPA(16 * (SL) + 12); }

__global__ void ctc_fwd_kernel(const int* __restrict__ y_true,
                               const float* __restrict__ y_pred,
                               float* __restrict__ out) {
    extern __shared__ float stg[];                 // 96 rows x 256 f32
    __shared__ __align__(8) unsigned long long mb[NSLOT];
    const int b = blockIdx.x, lane = threadIdx.x;
    const float* g = y_pred + (size_t)b * Tn * Cn;
    const uint32_t sbase = (uint32_t)__cvta_generic_to_shared(stg);
    const uint32_t mbase = (uint32_t)__cvta_generic_to_shared(mb);

    if (lane == 0) {
#pragma unroll
        for (int q = 0; q < NSLOT; q++)
            asm volatile("mbarrier.init.shared.b64 [%0], 1;" :: "r"(mbase + 8u * q) : "memory");
        asm volatile("fence.proxy.async.shared::cta;" ::: "memory");
    }
    __syncwarp();
#pragma unroll
    for (int q = 0; q < NSLOT; q++)                // prologue: quarters 0..5
        bulk_fill(mbase + 8u * q, sbase + q * 16384u, g + q * 4096, lane);

    const int l0 = y_true[b * Un + 2 * lane];
    const int l1 = y_true[b * Un + 2 * lane + 1];
    const int lp = __shfl_up_sync(0xffffffffu, l1, 1);
    const float sk1 = (lane == 0) ? 0.f : ((l0 != lp) ? 1.f : 0.f);
    const float sk3 = (l1 != l0) ? 1.f : 0.f;

    const float* pB = stg + BLANK;
    const float* p0 = stg + l0;
    const float* p1 = stg + l1;

    // ---- quarter 0 (slot 0, parity 0): t=0 init + t=1..3 peel + A B A
    mwait(mbase, 0u);
    __syncwarp();
    float a0 = 0.f, a1 = 0.f, a2 = 0.f, a3 = 0.f, a4 = 0.f;
    if (lane == 0) { a0 = pB[0] + EPSF; a1 = p0[0] + EPSF; }
#pragma unroll
    for (int t = 1; t < 4; t++) {
        float vB = fmaf(pB[t * Cn], Kc, EK);
        float v0 = fmaf(p0[t * Cn], Kc, EK);
        float v1 = fmaf(p1[t * Cn], Kc, EK);
        dp_step(a0, a1, a2, a3, a4, vB, v0, v1, sk1, sk3, lane);
    }
    float ls = 0.f, bf = 1.f;
    int   E  = 0;
    const float* gR = g + NSLOT * 4096;            // next stream quarter: 6

    GRPA(4); GRPB(8); GRPA(12);

    // ---- quarters 1..30: i=0..4, positions k=1..6 (q = 6i+k)
    // slots 1,2,3,4,5,0; parity pe=i&1 for k=1..5, po for k=6; refill iff q<=26.
#pragma unroll 1
    for (int i = 0; i < 5; i++) {
        const uint32_t pe = (uint32_t)(i & 1), po = pe ^ 1u;
        const int q6 = 6 * i;
        QBLK(1, pe, 0, (q6 + 1) <= 26);
        QBLK(2, pe, 1, (q6 + 2) <= 26);
        QBLK(3, pe, 2, (q6 + 3) <= 26);
        QBLK(4, pe, 3, (q6 + 4) <= 26);
        QBLK(5, pe, 4, (q6 + 5) <= 26);
        QBLK(0, po, 5, (q6 + 6) <= 26);
    }
    // ---- quarter 31 (slot 1, parity (31/6)&1 = 1), no refill
    QBLK(1, 1u, 0, false);

    // stored tail = true_tail * 256^511 * 2^-E (E exactly bookkept)
    if (lane == 31) {
        const float LN2 = 0.69314718055994530942f;
        out[b] = -(logf(a3 + a4) + (float)(E - 4088) * LN2);
    }
}

extern "C" void kernel_launch(void* const* d_in, const int* in_sizes, int n_in,
                              void* d_out, int out_size) {
    const int* y_true;
    const float* y_pred;
    if (in_sizes[0] == Bn * Un) {
        y_true = (const int*)d_in[0];
        y_pred = (const float*)d_in[1];
    } else {
        y_true = (const int*)d_in[1];
        y_pred = (const float*)d_in[0];
    }
    cudaFuncSetAttribute(ctc_fwd_kernel,
                         cudaFuncAttributeMaxDynamicSharedMemorySize, SMEM_TOTAL);
    ctc_fwd_kernel<<<Bn, 32, SMEM_TOTAL>>>(y_true, y_pred, (float*)d_out);
}